// round 15
// baseline (speedup 1.0000x reference)
#include <cuda_runtime.h>
#include <math.h>
#include <stdint.h>

#define THREADS 256

// smem layout (u32 units)
#define USTR 196   // row stride 784B == 16 mod 128 -> ldmatrix conflict-free
#define HSTR 36    // row stride 144B == 16 mod 128
#define OFF_U   0                  // sUhi [32][196] ; sUlo follows
#define ULO     6272
#define OFF_H   12544              // Hhi [32][36] + Hlo
#define HLO     1152
#define OFF_C2  (OFF_H + 2304)    // 14848
#define SMEM_U32 (OFF_C2 + 64)    // 14912
#define SMEM_BYTES (SMEM_U32 * 4)  // 59648 B -> 3 CTAs/SM

__device__ float g_c2[8 * 64];
// W1 in per-lane mma fragment order: [ks t 0..39][h hi/lo][vp 0..3][lane][4 regs]
__device__ __align__(16) unsigned gW1f[40 * 1024];
// W2 fragment order: [ks t 0..3][h][ng 0..3][lane][4 regs]
__device__ __align__(16) unsigned gW2f[4 * 1024];

// ---------------------------------------------------------------------------
__device__ __forceinline__ unsigned s2u(const void* p) {
    unsigned a;
    asm("{ .reg .u64 t; cvta.to.shared.u64 t, %1; cvt.u32.u64 %0, t; }" : "=r"(a) : "l"(p));
    return a;
}

// pack pair (e = even k, o = odd k) -> bf16x2 hi + bf16x2 lo residual
__device__ __forceinline__ void bsplit(float e, float o, unsigned& ph, unsigned& pl) {
    asm("cvt.rn.bf16x2.f32 %0, %1, %2;" : "=r"(ph) : "f"(o), "f"(e));
    float eh = __uint_as_float(ph << 16);
    float oh = __uint_as_float(ph & 0xffff0000u);
    asm("cvt.rn.bf16x2.f32 %0, %1, %2;" : "=r"(pl) : "f"(o - oh), "f"(e - eh));
}

__device__ __forceinline__ void mma_bf16(float* c,
                                         unsigned a0, unsigned a1, unsigned a2, unsigned a3,
                                         unsigned b0, unsigned b1)
{
    asm volatile(
        "mma.sync.aligned.m16n8k16.row.col.f32.bf16.bf16.f32 "
        "{%0,%1,%2,%3}, {%4,%5,%6,%7}, {%8,%9}, {%0,%1,%2,%3};"
        : "+f"(c[0]), "+f"(c[1]), "+f"(c[2]), "+f"(c[3])
        : "r"(a0), "r"(a1), "r"(a2), "r"(a3), "r"(b0), "r"(b1));
}

#define LDSM4(r0, r1, r2, r3, addr) \
    asm volatile("ldmatrix.sync.aligned.m8n8.x4.shared.b16 {%0,%1,%2,%3}, [%4];" \
                 : "=r"(r0), "=r"(r1), "=r"(r2), "=r"(r3) : "r"(addr))

__device__ __forceinline__ float gelu(float v) {
    return 0.5f * v * (1.0f + erff(v * 0.70710678118654752440f));
}

// ---------------------------------------------------------------------------
// prep (blocks 0..79): W1/W2 -> per-lane mma fragment order, bf16 hi/lo.
// ctx (block 80): attention collapses analytically (softmax pooling of a
// spatially constant value == the value). c2 = c + LN((c@Wv+bv)@Wo + bo + c).
// ---------------------------------------------------------------------------
__global__ void prep_ctx_kernel(const float* __restrict__ W1, const float* __restrict__ W2,
                                const float* __restrict__ c,
                                const float* __restrict__ Wv, const float* __restrict__ bv,
                                const float* __restrict__ Wo, const float* __restrict__ bo,
                                const float* __restrict__ lng, const float* __restrict__ lnb,
                                float* __restrict__ outc2)
{
    if (blockIdx.x < 80) {
        int item = blockIdx.x * THREADS + threadIdx.x;    // 0..20479
        {   // W1 fragments
            int comp = item & 3, lane = (item >> 2) & 31, vp = (item >> 7) & 3, t = item >> 9;
            int g = lane >> 2, tg = lane & 3;
            int v = vp * 2 + (comp >> 1), which = comp & 1;
            int n = v * 8 + g;
            int k0 = t * 16 + tg * 2 + which * 8;
            unsigned ph, pl;
            bsplit(W1[k0 * 64 + n], W1[(k0 + 1) * 64 + n], ph, pl);
            int base = ((t * 8 + vp) * 32 + lane) * 4 + comp;
            gW1f[base] = ph;
            gW1f[base + 512] = pl;
        }
        if (item < 2048) {   // W2 fragments
            int comp = item & 3, lane = (item >> 2) & 31, ng = (item >> 7) & 3, t = item >> 9;
            int g = lane >> 2, tg = lane & 3;
            int v = 2 * ng + (comp >> 1), which = comp & 1;
            int n = v * 8 + g;
            int k0 = t * 16 + tg * 2 + which * 8;
            unsigned ph, pl;
            bsplit(W2[k0 * 64 + n], W2[(k0 + 1) * 64 + n], ph, pl);
            int base = ((t * 8 + ng) * 32 + lane) * 4 + comp;
            gW2f[base] = ph;
            gW2f[base + 512] = pl;
        }
        return;
    }
    __shared__ float sv[8][64];
    __shared__ float st[8][64];
    int b = threadIdx.x >> 5;
    int lane = threadIdx.x & 31;

    #pragma unroll
    for (int oo = 0; oo < 2; oo++) {
        int o = lane + 32 * oo;
        float acc = bv[o];
        #pragma unroll 8
        for (int i = 0; i < 64; i++) acc += c[b * 64 + i] * Wv[i * 64 + o];
        sv[b][o] = acc;
    }
    __syncwarp();
    #pragma unroll
    for (int oo = 0; oo < 2; oo++) {
        int o = lane + 32 * oo;
        float acc = bo[o] + c[b * 64 + o];
        #pragma unroll 8
        for (int i = 0; i < 64; i++) acc += sv[b][i] * Wo[i * 64 + o];
        st[b][o] = acc;
    }
    __syncwarp();
    float t0 = st[b][lane], t1 = st[b][lane + 32];
    float s = t0 + t1;
    #pragma unroll
    for (int off = 16; off; off >>= 1) s += __shfl_xor_sync(0xffffffffu, s, off);
    float m = s * (1.0f / 64.0f);
    float d0 = t0 - m, d1 = t1 - m;
    float q = d0 * d0 + d1 * d1;
    #pragma unroll
    for (int off = 16; off; off >>= 1) q += __shfl_xor_sync(0xffffffffu, q, off);
    float inv = rsqrtf(q * (1.0f / 64.0f) + 1e-5f);
    #pragma unroll
    for (int oo = 0; oo < 2; oo++) {
        int o = lane + 32 * oo;
        float a = (st[b][o] - m) * inv * lng[o] + lnb[o];
        float v2 = c[b * 64 + o] + a;
        g_c2[b * 64 + o] = v2;
        outc2[b * 64 + o] = v2;
    }
}

// ---------------------------------------------------------------------------
// conv unit: one (dilation, x/c2) unit; thread owns channel pair, 16 pixels
// ---------------------------------------------------------------------------
__device__ __forceinline__ void conv_unit(
    const float* __restrict__ x, const float* __restrict__ pk, const float* sC2,
    unsigned* sUhi, unsigned* sUlo,
    int b, int h, int w0, int di, int isC2, int cpair, int half, int pc)
{
    int d = 1 << di;
    if (!isC2) {
        int ch = cpair << 1;
        const float* tp = pk + ((di << 7) + ch) * 9;
        float tap0[9], tap1[9];
        #pragma unroll
        for (int t9 = 0; t9 < 9; t9++) { tap0[t9] = tp[t9]; tap1[t9] = tp[9 + t9]; }
        const float* rp[3]; bool rv[3];
        #pragma unroll
        for (int t3 = 0; t3 < 3; t3++) {
            int hh = h + (t3 - 1) * d;
            rv[t3] = ((unsigned)hh < 128u);
            rp[t3] = x + (((size_t)((b << 7) + (hh & 127))) << 13) + ch;
        }
        #pragma unroll 4
        for (int j = 0; j < 16; j++) {
            int p = (j << 1) + half;
            int w = w0 + p;
            float a0 = 0.f, a1 = 0.f;
            #pragma unroll
            for (int t3 = 0; t3 < 3; t3++) {
                if (rv[t3]) {
                    #pragma unroll
                    for (int dx = 0; dx < 3; dx++) {
                        int ww = w + (dx - 1) * d;
                        if ((unsigned)ww < 128u) {
                            float2 v = *(const float2*)(rp[t3] + ((size_t)ww << 6));
                            a0 += v.x * tap0[t3 * 3 + dx];
                            a1 += v.y * tap1[t3 * 3 + dx];
                        }
                    }
                }
            }
            unsigned ph, pl; bsplit(a0, a1, ph, pl);
            sUhi[p * USTR + pc] = ph;
            sUlo[p * USTR + pc] = pl;
        }
    } else {
        int ch = 64 + (cpair << 1);
        const float* tp = pk + ((di << 7) + ch) * 9;
        float cs0[3] = {0, 0, 0}, cs1[3] = {0, 0, 0};
        #pragma unroll
        for (int t3 = 0; t3 < 3; t3++) {
            int hh = h + (t3 - 1) * d;
            if ((unsigned)hh < 128u) {
                #pragma unroll
                for (int dx = 0; dx < 3; dx++) {
                    cs0[dx] += tp[t3 * 3 + dx];
                    cs1[dx] += tp[9 + t3 * 3 + dx];
                }
            }
        }
        float c0 = sC2[ch - 64], c1 = sC2[ch - 63];
        #pragma unroll
        for (int j = 0; j < 16; j++) {
            int p = (j << 1) + half;
            int w = w0 + p;
            float k0 = 0.f, k1 = 0.f;
            #pragma unroll
            for (int dx = 0; dx < 3; dx++) {
                int ww = w + (dx - 1) * d;
                if ((unsigned)ww < 128u) { k0 += cs0[dx]; k1 += cs1[dx]; }
            }
            unsigned ph, pl; bsplit(c0 * k0, c1 * k1, ph, pl);
            sUhi[p * USTR + pc] = ph;
            sUlo[p * USTR + pc] = pl;
        }
    }
}

// ---------------------------------------------------------------------------
// main: 32-px blocks, 3 CTAs/SM. U built in two k-parts sharing one buffer
// (part0: x,c2,d1,d2 = 24 t; part1: d4,d8 = 16 t); acc persists in regs.
// GEMM1: warp grid 2m x 4ksplit, A via ldmatrix, W via fragment-order LDG.
// ---------------------------------------------------------------------------
__global__ __launch_bounds__(256, 3)
void nca_kernel(const float* __restrict__ x, const float* __restrict__ pk,
                const float* __restrict__ b1, const float* __restrict__ b2,
                float* __restrict__ y)
{
    extern __shared__ unsigned smem[];
    unsigned sbase = s2u(smem);
    unsigned* sUhi = smem + OFF_U;
    unsigned* sUlo = smem + ULO;
    float* sC2 = (float*)(smem + OFF_C2);

    int tid = threadIdx.x;
    int warp = tid >> 5, lane = tid & 31;
    int g = lane >> 2, tg = lane & 3;
    int mi = warp & 1;            // m half: rows mi*16 .. mi*16+15
    int kg = warp >> 1;           // k-split group (GEMM1) / n group (GEMM2)
    int m0 = mi << 4;

    int bi = blockIdx.x;
    int w0 = (bi & 3) << 5;
    int h  = (bi >> 2) & 127;
    int b  = bi >> 9;

    const size_t imgbase = ((size_t)((b << 7) + h)) << 13;

    // conv-unit mapping (used for both parts)
    int unit = tid >> 6;          // 0..3
    int cpair = (tid >> 1) & 31;
    int half = tid & 1;

    if (tid < 64) sC2[tid] = g_c2[b * 64 + tid];
    __syncthreads();

    // ==== part 0 production: x copy + c2 broadcast + dil1/dil2 convs ====
    #pragma unroll
    for (int j = 0; j < 8; j++) {
        int item = (j << 8) + tid;
        int pr = item & 63;
        int p  = item >> 6;
        float2 v;
        if (pr < 32) {
            v = *(const float2*)(x + imgbase + ((size_t)(w0 + p) << 6) + (pr << 1));
        } else {
            v = make_float2(sC2[(pr - 32) << 1], sC2[((pr - 32) << 1) + 1]);
        }
        unsigned ph, pl; bsplit(v.x, v.y, ph, pl);
        sUhi[p * USTR + pr] = ph;
        sUlo[p * USTR + pr] = pl;
    }
    // units: 0=d1x 1=d1c2 2=d2x 3=d2c2  -> pc = 64 + unit*32 + cpair
    conv_unit(x, pk, sC2, sUhi, sUlo, b, h, w0,
              unit >> 1, unit & 1, cpair, half, 64 + (unit << 5) + cpair);
    __syncthreads();

    // ---- ldmatrix lane addresses (A operand) ----
    int lane7 = lane & 7;
    unsigned rowA = m0 + lane7 + ((lane >> 3) & 1) * 8;
    unsigned kA4  = ((lane >> 4) & 1) * 4;
    unsigned aHiA = sbase + (rowA * USTR + kA4) * 4;

    float acc[8][4] = {};
    const uint4* __restrict__ w1f = (const uint4*)gW1f;

    // ==== GEMM1 part 0: t = kg*6 .. kg*6+5 (global t == local t) ====
    #pragma unroll 2
    for (int j = 0; j < 6; j++) {
        int t = kg * 6 + j;
        unsigned ah0, ah1, ah2, ah3, al0, al1, al2, al3;
        LDSM4(ah0, ah1, ah2, ah3, aHiA + t * 32);
        LDSM4(al0, al1, al2, al3, aHiA + ULO * 4 + t * 32);
        const uint4* bp = w1f + t * 256 + lane;
        #pragma unroll
        for (int vp = 0; vp < 4; vp++) {
            uint4 bh = bp[vp * 32];
            uint4 bl = bp[128 + vp * 32];
            mma_bf16(acc[2 * vp],     ah0, ah1, ah2, ah3, bh.x, bh.y);
            mma_bf16(acc[2 * vp],     al0, al1, al2, al3, bh.x, bh.y);
            mma_bf16(acc[2 * vp],     ah0, ah1, ah2, ah3, bl.x, bl.y);
            mma_bf16(acc[2 * vp + 1], ah0, ah1, ah2, ah3, bh.z, bh.w);
            mma_bf16(acc[2 * vp + 1], al0, al1, al2, al3, bh.z, bh.w);
            mma_bf16(acc[2 * vp + 1], ah0, ah1, ah2, ah3, bl.z, bl.w);
        }
    }
    __syncthreads();   // all warps done reading U part 0

    // ==== part 1 production: dil4/dil8 convs (kpairs 0..127 of buffer) ====
    // units: 0=d4x 1=d4c2 2=d8x 3=d8c2  -> pc = unit*32 + cpair
    conv_unit(x, pk, sC2, sUhi, sUlo, b, h, w0,
              2 + (unit >> 1), unit & 1, cpair, half, (unit << 5) + cpair);
    __syncthreads();

    // ==== GEMM1 part 1: local t = kg*4 .. kg*4+3, global W t = 24 + local ====
    #pragma unroll 2
    for (int j = 0; j < 4; j++) {
        int tl = kg * 4 + j;
        unsigned ah0, ah1, ah2, ah3, al0, al1, al2, al3;
        LDSM4(ah0, ah1, ah2, ah3, aHiA + tl * 32);
        LDSM4(al0, al1, al2, al3, aHiA + ULO * 4 + tl * 32);
        const uint4* bp = w1f + (24 + tl) * 256 + lane;
        #pragma unroll
        for (int vp = 0; vp < 4; vp++) {
            uint4 bh = bp[vp * 32];
            uint4 bl = bp[128 + vp * 32];
            mma_bf16(acc[2 * vp],     ah0, ah1, ah2, ah3, bh.x, bh.y);
            mma_bf16(acc[2 * vp],     al0, al1, al2, al3, bh.x, bh.y);
            mma_bf16(acc[2 * vp],     ah0, ah1, ah2, ah3, bl.x, bl.y);
            mma_bf16(acc[2 * vp + 1], ah0, ah1, ah2, ah3, bh.z, bh.w);
            mma_bf16(acc[2 * vp + 1], al0, al1, al2, al3, bh.z, bh.w);
            mma_bf16(acc[2 * vp + 1], ah0, ah1, ah2, ah3, bl.z, bl.w);
        }
    }
    __syncthreads();   // U dead; reduction region aliases it

    // ---- k-split reduction: all warps dump acc (stride-33 rotation) ----
    {
        unsigned* srd = smem + warp * 1056 + lane * 33;
        #pragma unroll
        for (int idx = 0; idx < 32; idx++)
            srd[idx] = __float_as_uint(acc[idx >> 2][idx & 3]);
    }
    __syncthreads();

    // ---- reduce 4 partials + bias + GELU -> H (warp (mi,kg) owns cols kg*16..) ----
    unsigned* sHhi = smem + OFF_H;
    unsigned* sHlo = smem + OFF_H + HLO;
    #pragma unroll
    for (int vv = 0; vv < 2; vv++) {
        int v = 2 * kg + vv;
        float val[4] = {0, 0, 0, 0};
        #pragma unroll
        for (int kq = 0; kq < 4; kq++) {
            const unsigned* srd = smem + (kq * 2 + mi) * 1056 + lane * 33 + v * 4;
            val[0] += __uint_as_float(srd[0]);
            val[1] += __uint_as_float(srd[1]);
            val[2] += __uint_as_float(srd[2]);
            val[3] += __uint_as_float(srd[3]);
        }
        int col = v * 8 + tg * 2;
        float2 bb = *(const float2*)(b1 + col);
        float h0 = gelu(val[0] + bb.x);
        float h1 = gelu(val[1] + bb.y);
        float h2 = gelu(val[2] + bb.x);
        float h3 = gelu(val[3] + bb.y);
        int hp = v * 4 + tg;
        unsigned ph, pl;
        bsplit(h0, h1, ph, pl);
        sHhi[(m0 + g) * HSTR + hp] = ph;
        sHlo[(m0 + g) * HSTR + hp] = pl;
        bsplit(h2, h3, ph, pl);
        sHhi[(m0 + g + 8) * HSTR + hp] = ph;
        sHlo[(m0 + g + 8) * HSTR + hp] = pl;
    }
    __syncthreads();

    // ---- GEMM2: grid 2m x 4n (kg doubles as ng); H via LDSM, W2 via LDG ----
    int n0 = kg << 4;
    unsigned hA = sbase + (OFF_H + rowA * HSTR + kA4) * 4;
    const uint4* __restrict__ w2f = (const uint4*)gW2f;
    float o[2][4] = {};
    #pragma unroll
    for (int t = 0; t < 4; t++) {
        unsigned ah0, ah1, ah2, ah3, al0, al1, al2, al3;
        LDSM4(ah0, ah1, ah2, ah3, hA + t * 32);
        LDSM4(al0, al1, al2, al3, hA + HLO * 4 + t * 32);
        const uint4* bp = w2f + t * 256 + kg * 32 + lane;
        uint4 bh = bp[0];
        uint4 bl = bp[128];
        mma_bf16(o[0], ah0, ah1, ah2, ah3, bh.x, bh.y);
        mma_bf16(o[0], al0, al1, al2, al3, bh.x, bh.y);
        mma_bf16(o[0], ah0, ah1, ah2, ah3, bl.x, bl.y);
        mma_bf16(o[1], ah0, ah1, ah2, ah3, bh.z, bh.w);
        mma_bf16(o[1], al0, al1, al2, al3, bh.z, bh.w);
        mma_bf16(o[1], ah0, ah1, ah2, ah3, bl.z, bl.w);
    }

    // ---- epilogue: bias + store ----
    const size_t pixbase = (((size_t)((b << 7) + h)) << 7) + w0;
    #pragma unroll
    for (int nt = 0; nt < 2; nt++) {
        int col = n0 + (nt << 3) + (tg << 1);
        float2 bb = *(const float2*)(b2 + col);
        *(float2*)(y + ((pixbase + m0 + g) << 6) + col) =
            make_float2(o[nt][0] + bb.x, o[nt][1] + bb.y);
        *(float2*)(y + ((pixbase + m0 + g + 8) << 6) + col) =
            make_float2(o[nt][2] + bb.x, o[nt][3] + bb.y);
    }
}

// ---------------------------------------------------------------------------
extern "C" void kernel_launch(void* const* d_in, const int* in_sizes, int n_in,
                              void* d_out, int out_size)
{
    const float* x   = (const float*)d_in[0];
    const float* c   = (const float*)d_in[1];
    const float* Wv  = (const float*)d_in[6];
    const float* bv  = (const float*)d_in[7];
    const float* Wo  = (const float*)d_in[8];
    const float* bo  = (const float*)d_in[9];
    const float* lng = (const float*)d_in[10];
    const float* lnb = (const float*)d_in[11];
    const float* pk  = (const float*)d_in[12];
    const float* W1  = (const float*)d_in[13];
    const float* b1  = (const float*)d_in[14];
    const float* W2  = (const float*)d_in[15];
    const float* b2  = (const float*)d_in[16];

    float* y     = (float*)d_out;
    float* outc2 = y + (size_t)8 * 128 * 128 * 64;

    prep_ctx_kernel<<<81, THREADS>>>(W1, W2, c, Wv, bv, Wo, bo, lng, lnb, outc2);

    cudaFuncSetAttribute(nca_kernel, cudaFuncAttributeMaxDynamicSharedMemorySize, SMEM_BYTES);
    nca_kernel<<<4096, THREADS, SMEM_BYTES>>>(x, pk, b1, b2, y);
}

// round 16
// speedup vs baseline: 1.2604x; 1.2604x over previous
#include <cuda_runtime.h>
#include <math.h>
#include <stdint.h>

#define THREADS 256

// smem layout (u32 units)
#define USTR 324   // row stride 1296B == 16 mod 128 -> ldmatrix conflict-free
#define HSTR 36    // row stride 144B  == 16 mod 128
#define OFF_U   0          // sUhi [32][324]
#define ULO     10368      // sUlo
#define OFF_H   20736      // Hhi [32][36] + Hlo
#define HLO     1152
#define OFF_C2  23040
#define SMEM_U32 23104
#define SMEM_BYTES (SMEM_U32 * 4)   // 92416 B -> 2 CTAs/SM

__device__ float g_c2[8 * 64];
// W1 in per-lane mma fragment order: [ks t 0..39][h hi/lo][vp 0..3][lane][4 regs]
__device__ __align__(16) unsigned gW1f[40 * 1024];
// W2 fragment order: [ks t 0..3][h][ng 0..3][lane][4 regs]
__device__ __align__(16) unsigned gW2f[4 * 1024];

// ---------------------------------------------------------------------------
__device__ __forceinline__ unsigned s2u(const void* p) {
    unsigned a;
    asm("{ .reg .u64 t; cvta.to.shared.u64 t, %1; cvt.u32.u64 %0, t; }" : "=r"(a) : "l"(p));
    return a;
}

// pack pair (e = even k, o = odd k) -> bf16x2 hi + bf16x2 lo residual
__device__ __forceinline__ void bsplit(float e, float o, unsigned& ph, unsigned& pl) {
    asm("cvt.rn.bf16x2.f32 %0, %1, %2;" : "=r"(ph) : "f"(o), "f"(e));
    float eh = __uint_as_float(ph << 16);
    float oh = __uint_as_float(ph & 0xffff0000u);
    asm("cvt.rn.bf16x2.f32 %0, %1, %2;" : "=r"(pl) : "f"(o - oh), "f"(e - eh));
}

__device__ __forceinline__ void mma_bf16(float* c,
                                         unsigned a0, unsigned a1, unsigned a2, unsigned a3,
                                         unsigned b0, unsigned b1)
{
    asm volatile(
        "mma.sync.aligned.m16n8k16.row.col.f32.bf16.bf16.f32 "
        "{%0,%1,%2,%3}, {%4,%5,%6,%7}, {%8,%9}, {%0,%1,%2,%3};"
        : "+f"(c[0]), "+f"(c[1]), "+f"(c[2]), "+f"(c[3])
        : "r"(a0), "r"(a1), "r"(a2), "r"(a3), "r"(b0), "r"(b1));
}

#define LDSM4(r0, r1, r2, r3, addr) \
    asm volatile("ldmatrix.sync.aligned.m8n8.x4.shared.b16 {%0,%1,%2,%3}, [%4];" \
                 : "=r"(r0), "=r"(r1), "=r"(r2), "=r"(r3) : "r"(addr))

__device__ __forceinline__ float gelu(float v) {
    return 0.5f * v * (1.0f + erff(v * 0.70710678118654752440f));
}

// ---------------------------------------------------------------------------
// prep (blocks 0..79): W1/W2 -> per-lane mma fragment order, bf16 hi/lo.
// ctx (block 80): attention collapses analytically (softmax pooling of a
// spatially constant value == the value). c2 = c + LN((c@Wv+bv)@Wo + bo + c).
// ---------------------------------------------------------------------------
__global__ void prep_ctx_kernel(const float* __restrict__ W1, const float* __restrict__ W2,
                                const float* __restrict__ c,
                                const float* __restrict__ Wv, const float* __restrict__ bv,
                                const float* __restrict__ Wo, const float* __restrict__ bo,
                                const float* __restrict__ lng, const float* __restrict__ lnb,
                                float* __restrict__ outc2)
{
    if (blockIdx.x < 80) {
        int item = blockIdx.x * THREADS + threadIdx.x;    // 0..20479
        {   // W1 fragments
            int comp = item & 3, lane = (item >> 2) & 31, vp = (item >> 7) & 3, t = item >> 9;
            int g = lane >> 2, tg = lane & 3;
            int v = vp * 2 + (comp >> 1), which = comp & 1;
            int n = v * 8 + g;
            int k0 = t * 16 + tg * 2 + which * 8;
            unsigned ph, pl;
            bsplit(W1[k0 * 64 + n], W1[(k0 + 1) * 64 + n], ph, pl);
            int base = ((t * 8 + vp) * 32 + lane) * 4 + comp;
            gW1f[base] = ph;
            gW1f[base + 512] = pl;
        }
        if (item < 2048) {   // W2 fragments
            int comp = item & 3, lane = (item >> 2) & 31, ng = (item >> 7) & 3, t = item >> 9;
            int g = lane >> 2, tg = lane & 3;
            int v = 2 * ng + (comp >> 1), which = comp & 1;
            int n = v * 8 + g;
            int k0 = t * 16 + tg * 2 + which * 8;
            unsigned ph, pl;
            bsplit(W2[k0 * 64 + n], W2[(k0 + 1) * 64 + n], ph, pl);
            int base = ((t * 8 + ng) * 32 + lane) * 4 + comp;
            gW2f[base] = ph;
            gW2f[base + 512] = pl;
        }
        return;
    }
    __shared__ float sv[8][64];
    __shared__ float st[8][64];
    int b = threadIdx.x >> 5;
    int lane = threadIdx.x & 31;

    #pragma unroll
    for (int oo = 0; oo < 2; oo++) {
        int o = lane + 32 * oo;
        float acc = bv[o];
        #pragma unroll 8
        for (int i = 0; i < 64; i++) acc += c[b * 64 + i] * Wv[i * 64 + o];
        sv[b][o] = acc;
    }
    __syncwarp();
    #pragma unroll
    for (int oo = 0; oo < 2; oo++) {
        int o = lane + 32 * oo;
        float acc = bo[o] + c[b * 64 + o];
        #pragma unroll 8
        for (int i = 0; i < 64; i++) acc += sv[b][i] * Wo[i * 64 + o];
        st[b][o] = acc;
    }
    __syncwarp();
    float t0 = st[b][lane], t1 = st[b][lane + 32];
    float s = t0 + t1;
    #pragma unroll
    for (int off = 16; off; off >>= 1) s += __shfl_xor_sync(0xffffffffu, s, off);
    float m = s * (1.0f / 64.0f);
    float d0 = t0 - m, d1 = t1 - m;
    float q = d0 * d0 + d1 * d1;
    #pragma unroll
    for (int off = 16; off; off >>= 1) q += __shfl_xor_sync(0xffffffffu, q, off);
    float inv = rsqrtf(q * (1.0f / 64.0f) + 1e-5f);
    #pragma unroll
    for (int oo = 0; oo < 2; oo++) {
        int o = lane + 32 * oo;
        float a = (st[b][o] - m) * inv * lng[o] + lnb[o];
        float v2 = c[b * 64 + o] + a;
        g_c2[b * 64 + o] = v2;
        outc2[b * 64 + o] = v2;
    }
}

// ---------------------------------------------------------------------------
// main: 32-px blocks, 2 CTAs/SM, full U in smem (R10 base). GEMM1 warp grid:
// 8-way k-split, each warp covers all 32 rows x 64 cols for its 5 t-steps ->
// W1 fragments read exactly ONCE per block (halves W L2 traffic vs R10).
// ---------------------------------------------------------------------------
__global__ __launch_bounds__(256, 2)
void nca_kernel(const float* __restrict__ x, const float* __restrict__ pk,
                const float* __restrict__ b1, const float* __restrict__ b2,
                float* __restrict__ y)
{
    extern __shared__ unsigned smem[];
    unsigned sbase = s2u(smem);
    unsigned* sUhi = smem + OFF_U;
    unsigned* sUlo = smem + ULO;
    float* sC2 = (float*)(smem + OFF_C2);

    int tid = threadIdx.x;
    int warp = tid >> 5, lane = tid & 31;
    int g = lane >> 2, tg = lane & 3;

    int bi = blockIdx.x;
    int w0 = (bi & 3) << 5;
    int h  = (bi >> 2) & 127;
    int b  = bi >> 9;

    const size_t imgbase = ((size_t)((b << 7) + h)) << 13;

    if (tid < 64) sC2[tid] = g_c2[b * 64 + tid];
    __syncthreads();

    // ---- phase 1a: x copy (kpairs 0-31) + c2 broadcast (kpairs 32-63) ----
    #pragma unroll
    for (int j = 0; j < 8; j++) {
        int item = (j << 8) + tid;
        int pr = item & 63;
        int p  = item >> 6;
        float2 v;
        if (pr < 32) {
            v = *(const float2*)(x + imgbase + ((size_t)(w0 + p) << 6) + (pr << 1));
        } else {
            v = make_float2(sC2[(pr - 32) << 1], sC2[((pr - 32) << 1) + 1]);
        }
        unsigned ph, pl; bsplit(v.x, v.y, ph, pl);
        sUhi[p * USTR + pr] = ph;
        sUlo[p * USTR + pr] = pl;
    }

    // ---- phase 1b: context half (conv of constant = c2 * masked tap sums) ----
    {
        int cpair = tid >> 1, half = tid & 1;
        int di = cpair >> 5, cq = cpair & 31;
        int ch = 64 + (cq << 1);
        int d  = 1 << di;
        int pc = 96 + (di << 6) + cq;
        const float* tp = pk + ((di << 7) + ch) * 9;
        float cs0[3] = {0, 0, 0}, cs1[3] = {0, 0, 0};
        #pragma unroll
        for (int t3 = 0; t3 < 3; t3++) {
            int hh = h + (t3 - 1) * d;
            if ((unsigned)hh < 128u) {
                #pragma unroll
                for (int dx = 0; dx < 3; dx++) {
                    cs0[dx] += tp[t3 * 3 + dx];
                    cs1[dx] += tp[9 + t3 * 3 + dx];
                }
            }
        }
        float c0 = sC2[ch - 64], c1 = sC2[ch - 63];
        #pragma unroll
        for (int j = 0; j < 16; j++) {
            int p = (j << 1) + half;
            int w = w0 + p;
            float k0 = 0.f, k1 = 0.f;
            #pragma unroll
            for (int dx = 0; dx < 3; dx++) {
                int ww = w + (dx - 1) * d;
                if ((unsigned)ww < 128u) { k0 += cs0[dx]; k1 += cs1[dx]; }
            }
            unsigned ph, pl; bsplit(c0 * k0, c1 * k1, ph, pl);
            sUhi[p * USTR + pc] = ph;
            sUlo[p * USTR + pc] = pl;
        }
    }

    // ---- phase 1c: real depthwise dilated conv (x half) ----
    {
        int cpair = tid >> 1, half = tid & 1;
        int di = cpair >> 5, chp = cpair & 31;
        int ch = chp << 1;
        int d  = 1 << di;
        int pc = 64 + (di << 6) + chp;
        const float* tp = pk + ((di << 7) + ch) * 9;
        float tap0[9], tap1[9];
        #pragma unroll
        for (int t9 = 0; t9 < 9; t9++) { tap0[t9] = tp[t9]; tap1[t9] = tp[9 + t9]; }
        const float* rp[3]; bool rv[3];
        #pragma unroll
        for (int t3 = 0; t3 < 3; t3++) {
            int hh = h + (t3 - 1) * d;
            rv[t3] = ((unsigned)hh < 128u);
            rp[t3] = x + (((size_t)((b << 7) + (hh & 127))) << 13) + ch;
        }
        #pragma unroll 4
        for (int j = 0; j < 16; j++) {
            int p = (j << 1) + half;
            int w = w0 + p;
            float a0 = 0.f, a1 = 0.f;
            #pragma unroll
            for (int t3 = 0; t3 < 3; t3++) {
                if (rv[t3]) {
                    #pragma unroll
                    for (int dx = 0; dx < 3; dx++) {
                        int ww = w + (dx - 1) * d;
                        if ((unsigned)ww < 128u) {
                            float2 v = *(const float2*)(rp[t3] + ((size_t)ww << 6));
                            a0 += v.x * tap0[t3 * 3 + dx];
                            a1 += v.y * tap1[t3 * 3 + dx];
                        }
                    }
                }
            }
            unsigned ph, pl; bsplit(a0, a1, ph, pl);
            sUhi[p * USTR + pc] = ph;
            sUlo[p * USTR + pc] = pl;
        }
    }
    __syncthreads();

    // ---- ldmatrix lane addresses ----
    int lane7 = lane & 7;
    unsigned rowBase = lane7 + ((lane >> 3) & 1) * 8;   // 0..15
    unsigned kA4  = ((lane >> 4) & 1) * 4;
    unsigned aHiA = sbase + (rowBase * USTR + kA4) * 4;

    // ---- GEMM1: warp = k-split group (t = warp*5 .. warp*5+4), m32 x n64 ----
    float acc[2][8][4] = {};
    const uint4* __restrict__ w1f = (const uint4*)gW1f;

    #pragma unroll 2
    for (int j = 0; j < 5; j++) {
        int t = warp * 5 + j;
        unsigned ah0[4], ah1[4], al0[4], al1[4];
        LDSM4(ah0[0], ah0[1], ah0[2], ah0[3], aHiA + t * 32);                      // rows 0-15 hi
        LDSM4(ah1[0], ah1[1], ah1[2], ah1[3], aHiA + 16 * USTR * 4 + t * 32);      // rows 16-31 hi
        LDSM4(al0[0], al0[1], al0[2], al0[3], aHiA + ULO * 4 + t * 32);            // rows 0-15 lo
        LDSM4(al1[0], al1[1], al1[2], al1[3], aHiA + (ULO + 16 * USTR) * 4 + t * 32);
        const uint4* bp = w1f + t * 256 + lane;
        #pragma unroll
        for (int vp = 0; vp < 4; vp++) {
            uint4 bh = bp[vp * 32];
            uint4 bl = bp[128 + vp * 32];
            // rows 0-15
            mma_bf16(acc[0][2 * vp],     ah0[0], ah0[1], ah0[2], ah0[3], bh.x, bh.y);
            mma_bf16(acc[0][2 * vp],     al0[0], al0[1], al0[2], al0[3], bh.x, bh.y);
            mma_bf16(acc[0][2 * vp],     ah0[0], ah0[1], ah0[2], ah0[3], bl.x, bl.y);
            mma_bf16(acc[0][2 * vp + 1], ah0[0], ah0[1], ah0[2], ah0[3], bh.z, bh.w);
            mma_bf16(acc[0][2 * vp + 1], al0[0], al0[1], al0[2], al0[3], bh.z, bh.w);
            mma_bf16(acc[0][2 * vp + 1], ah0[0], ah0[1], ah0[2], ah0[3], bl.z, bl.w);
            // rows 16-31
            mma_bf16(acc[1][2 * vp],     ah1[0], ah1[1], ah1[2], ah1[3], bh.x, bh.y);
            mma_bf16(acc[1][2 * vp],     al1[0], al1[1], al1[2], al1[3], bh.x, bh.y);
            mma_bf16(acc[1][2 * vp],     ah1[0], ah1[1], ah1[2], ah1[3], bl.x, bl.y);
            mma_bf16(acc[1][2 * vp + 1], ah1[0], ah1[1], ah1[2], ah1[3], bh.z, bh.w);
            mma_bf16(acc[1][2 * vp + 1], al1[0], al1[1], al1[2], al1[3], bh.z, bh.w);
            mma_bf16(acc[1][2 * vp + 1], ah1[0], ah1[1], ah1[2], ah1[3], bl.z, bl.w);
        }
    }
    __syncthreads();   // U dead; reduction region aliases it

    // ---- k-split reduction dump: region [warp][lane][68] (STS.128, cf) ----
    {
        const float4* af = (const float4*)acc;
        float4* dp = (float4*)(smem + warp * 2176 + lane * 68);
        #pragma unroll
        for (int i = 0; i < 16; i++) dp[i] = af[i];
    }
    __syncthreads();

    // ---- reduce 8 partials + bias + GELU -> H. thread: row r, cols jcol*8.. ----
    unsigned* sHhi = smem + OFF_H;
    unsigned* sHlo = smem + OFF_H + HLO;
    {
        int r = tid >> 3, jcol = tid & 7;
        int off = ((r & 7) << 2) * 68 + ((r >> 4) << 5) + (jcol << 2) + (((r >> 3) & 1) << 1);
        float v[8] = {0, 0, 0, 0, 0, 0, 0, 0};
        #pragma unroll
        for (int kq = 0; kq < 8; kq++) {
            const float* rg = (const float*)(smem + kq * 2176) + off;
            #pragma unroll
            for (int u = 0; u < 4; u++) {
                float2 pv = *(const float2*)(rg + u * 68);
                v[u * 2] += pv.x;
                v[u * 2 + 1] += pv.y;
            }
        }
        #pragma unroll
        for (int u = 0; u < 4; u++) {
            int col = (jcol << 3) + (u << 1);
            float2 bb = *(const float2*)(b1 + col);
            float h0 = gelu(v[u * 2] + bb.x);
            float h1 = gelu(v[u * 2 + 1] + bb.y);
            unsigned ph, pl;
            bsplit(h0, h1, ph, pl);
            sHhi[r * HSTR + (jcol << 2) + u] = ph;
            sHlo[r * HSTR + (jcol << 2) + u] = pl;
        }
    }
    __syncthreads();

    // ---- GEMM2: grid 2m x 4n; H via LDSM, W2 via fragment LDG ----
    int g2mi = warp & 1, g2n = warp >> 1;
    int m0 = g2mi << 4, n0 = g2n << 4;
    unsigned rowA2 = m0 + rowBase;
    unsigned hA = sbase + (OFF_H + rowA2 * HSTR + kA4) * 4;
    const uint4* __restrict__ w2f = (const uint4*)gW2f;
    float o[2][4] = {{0, 0, 0, 0}, {0, 0, 0, 0}};
    #pragma unroll
    for (int t = 0; t < 4; t++) {
        unsigned ah0, ah1, ah2, ah3, al0, al1, al2, al3;
        LDSM4(ah0, ah1, ah2, ah3, hA + t * 32);
        LDSM4(al0, al1, al2, al3, hA + HLO * 4 + t * 32);
        const uint4* bp = w2f + t * 256 + g2n * 32 + lane;
        uint4 bh = bp[0];
        uint4 bl = bp[128];
        mma_bf16(o[0], ah0, ah1, ah2, ah3, bh.x, bh.y);
        mma_bf16(o[0], al0, al1, al2, al3, bh.x, bh.y);
        mma_bf16(o[0], ah0, ah1, ah2, ah3, bl.x, bl.y);
        mma_bf16(o[1], ah0, ah1, ah2, ah3, bh.z, bh.w);
        mma_bf16(o[1], al0, al1, al2, al3, bh.z, bh.w);
        mma_bf16(o[1], ah0, ah1, ah2, ah3, bl.z, bl.w);
    }

    // ---- epilogue: bias + store ----
    const size_t pixbase = (((size_t)((b << 7) + h)) << 7) + w0;
    #pragma unroll
    for (int nt = 0; nt < 2; nt++) {
        int col = n0 + (nt << 3) + (tg << 1);
        float2 bb = *(const float2*)(b2 + col);
        *(float2*)(y + ((pixbase + m0 + g) << 6) + col) =
            make_float2(o[nt][0] + bb.x, o[nt][1] + bb.y);
        *(float2*)(y + ((pixbase + m0 + g + 8) << 6) + col) =
            make_float2(o[nt][2] + bb.x, o[nt][3] + bb.y);
    }
}

// ---------------------------------------------------------------------------
extern "C" void kernel_launch(void* const* d_in, const int* in_sizes, int n_in,
                              void* d_out, int out_size)
{
    const float* x   = (const float*)d_in[0];
    const float* c   = (const float*)d_in[1];
    const float* Wv  = (const float*)d_in[6];
    const float* bv  = (const float*)d_in[7];
    const float* Wo  = (const float*)d_in[8];
    const float* bo  = (const float*)d_in[9];
    const float* lng = (const float*)d_in[10];
    const float* lnb = (const float*)d_in[11];
    const float* pk  = (const float*)d_in[12];
    const float* W1  = (const float*)d_in[13];
    const float* b1  = (const float*)d_in[14];
    const float* W2  = (const float*)d_in[15];
    const float* b2  = (const float*)d_in[16];

    float* y     = (float*)d_out;
    float* outc2 = y + (size_t)8 * 128 * 128 * 64;

    prep_ctx_kernel<<<81, THREADS>>>(W1, W2, c, Wv, bv, Wo, bo, lng, lnb, outc2);

    cudaFuncSetAttribute(nca_kernel, cudaFuncAttributeMaxDynamicSharedMemorySize, SMEM_BYTES);
    nca_kernel<<<4096, THREADS, SMEM_BYTES>>>(x, pk, b1, b2, y);
}